// round 4
// baseline (speedup 1.0000x reference)
#include <cuda_runtime.h>
#include <math.h>
#include <stdint.h>

#define NB 8
#define NN 2048
#define ND 128
#define BK 32
#define NIT (NN / BK)   // 64 k-chunks

// ---- scratch (__device__ globals: allocation-guard safe) ----
__device__ float g_dist[(size_t)NB * NN * NN];   // 134 MB pairwise distances (tf32-rounded)
__device__ float g_dinv[NB * NN];                // rsqrt(degree)
__device__ float g_zT[(size_t)NB * ND * NN];     // transposed dinv*(h@Wg^T): [b][d][m] (tf32)
__device__ float g_mean[NB * ND];
__device__ float g_rstd[NB * ND];

__device__ __forceinline__ uint32_t smem_u32(const void* p) {
    uint32_t a;
    asm("{ .reg .u64 t; cvta.to.shared.u64 t, %1; cvt.u32.u64 %0, t; }" : "=r"(a) : "l"(p));
    return a;
}
__device__ __forceinline__ float f2tf32(float x) {
    uint32_t r;
    asm("cvt.rna.tf32.f32 %0, %1;" : "=r"(r) : "f"(x));
    return __uint_as_float(r);
}

// FMA-only sqrt (avoids MUFU throughput wall on 33.5M sqrts)
__device__ __forceinline__ float fast_sqrt(float x) {
    float xh = 0.5f * x;
    float y = __int_as_float(0x5f3759df - (__float_as_int(x) >> 1));
    y = y * (1.5f - xh * y * y);
    y = y * (1.5f - xh * y * y);
    y = y * (1.5f - xh * y * y);
    return x * y;
}

// ---------------------------------------------------------------------------
// Kernel 1: dist rows (tf32-rounded) + degree -> dinv
// ---------------------------------------------------------------------------
__global__ void k_dist(const float* __restrict__ inst) {
    int n = blockIdx.x, b = blockIdx.y;
    const float2* xb = (const float2*)(inst + (size_t)b * NN * 2);
    float2 xn = xb[n];
    float sqn = xn.x * xn.x + xn.y * xn.y;
    float* drow = g_dist + (size_t)(b * NN + n) * NN;
    float acc = 0.f;
    for (int m = threadIdx.x; m < NN; m += 256) {
        float2 xm = xb[m];
        float sqm = xm.x * xm.x + xm.y * xm.y;
        float dot = xn.x * xm.x + xn.y * xm.y;
        float d2 = sqn + sqm - 2.f * dot;
        float d = (d2 > 0.f) ? fast_sqrt(d2) : 0.f;
        drow[m] = f2tf32(d);      // pre-rounded for the tf32 MMA
        acc += d;                 // degree in full precision
    }
    __shared__ float red[256];
    red[threadIdx.x] = acc;
    __syncthreads();
    for (int s = 128; s > 0; s >>= 1) {
        if (threadIdx.x < s) red[threadIdx.x] += red[threadIdx.x + s];
        __syncthreads();
    }
    if (threadIdx.x == 0)
        g_dinv[b * NN + n] = rsqrtf(1.0f + red[0]);
}

// ---------------------------------------------------------------------------
// Kernel 2: h0 = instance @ Wn^T + bn
// ---------------------------------------------------------------------------
__global__ void k_proj(const float* __restrict__ inst, const float* __restrict__ Wn,
                       const float* __restrict__ bn, float* __restrict__ h) {
    int idx = blockIdx.x * 256 + threadIdx.x;
    int d = idx & (ND - 1);
    int row = idx >> 7;
    float2 x = ((const float2*)inst)[row];
    h[idx] = x.x * Wn[2 * d] + x.y * Wn[2 * d + 1] + bn[d];
}

// ---------------------------------------------------------------------------
// Kernel 3: zT[b][e][m] = dinv[m] * sum_d h[m,d] * Wg[e,d]  (transposed, tf32)
// ---------------------------------------------------------------------------
__global__ void __launch_bounds__(256) k_z(const float* __restrict__ h,
                                           const float* __restrict__ Wg) {
    __shared__ float hT[32][132];
    __shared__ float wT[32][132];
    int t = threadIdx.x;
    int row0 = blockIdx.x * 128;  // global row over NB*NN
    int rg = t >> 4, cg = t & 15;
    float acc[8][8];
#pragma unroll
    for (int i = 0; i < 8; i++)
#pragma unroll
        for (int j = 0; j < 8; j++) acc[i][j] = 0.f;

    for (int dc = 0; dc < ND; dc += 32) {
        __syncthreads();
#pragma unroll
        for (int k = t; k < 128 * 32; k += 256) {
            int r = k >> 5, dd = k & 31;
            hT[dd][r] = h[(size_t)(row0 + r) * ND + dc + dd];
        }
#pragma unroll
        for (int k = t; k < 128 * 32; k += 256) {
            int e = k >> 5, dd = k & 31;
            wT[dd][e] = Wg[e * ND + dc + dd];
        }
        __syncthreads();
#pragma unroll
        for (int dd = 0; dd < 32; dd++) {
            float4 a0 = *(const float4*)&hT[dd][8 * rg];
            float4 a1 = *(const float4*)&hT[dd][8 * rg + 4];
            float4 b0 = *(const float4*)&wT[dd][8 * cg];
            float4 b1 = *(const float4*)&wT[dd][8 * cg + 4];
            float a[8] = {a0.x, a0.y, a0.z, a0.w, a1.x, a1.y, a1.z, a1.w};
            float bb[8] = {b0.x, b0.y, b0.z, b0.w, b1.x, b1.y, b1.z, b1.w};
#pragma unroll
            for (int i = 0; i < 8; i++)
#pragma unroll
                for (int j = 0; j < 8; j++)
                    acc[i][j] = fmaf(a[i], bb[j], acc[i][j]);
        }
    }
    int b = row0 >> 11;            // NN = 2048
    int m0 = (row0 & (NN - 1)) + 8 * rg;
    float* zTb = g_zT + (size_t)b * ND * NN;
    float dvv[8];
#pragma unroll
    for (int i = 0; i < 8; i++) dvv[i] = g_dinv[b * NN + m0 + i];
#pragma unroll
    for (int j = 0; j < 8; j++) {
        int d = 8 * cg + j;
        float4 v0, v1;
        v0.x = f2tf32(acc[0][j] * dvv[0]); v0.y = f2tf32(acc[1][j] * dvv[1]);
        v0.z = f2tf32(acc[2][j] * dvv[2]); v0.w = f2tf32(acc[3][j] * dvv[3]);
        v1.x = f2tf32(acc[4][j] * dvv[4]); v1.y = f2tf32(acc[5][j] * dvv[5]);
        v1.z = f2tf32(acc[6][j] * dvv[6]); v1.w = f2tf32(acc[7][j] * dvv[7]);
        *(float4*)&zTb[(size_t)d * NN + m0] = v0;
        *(float4*)&zTb[(size_t)d * NN + m0 + 4] = v1;
    }
}

// ---------------------------------------------------------------------------
// Kernel 4: tf32 mma.sync GEMM, 512 threads, CTA-internal split-K.
// h[n,:] = tanh( dinv[n]*(dist[n,:] @ z + z[n,:]) + bg ) + h[n,:]
// CTA 128x128, 16 warps = 2 K-groups x 8 warps (2x4, warp tile 64x32).
// Group g computes s-steps {2g, 2g+1} of every BK=32 chunk (shared stages).
// 3-stage cp.async pipeline, ONE __syncthreads per iteration.
// Partial accums combined through smem; group 0 does the fused epilogue.
// ---------------------------------------------------------------------------
__global__ void __launch_bounds__(512) k_gemm_mma(float* __restrict__ h,
                                                  const float* __restrict__ bg_l) {
    extern __shared__ float sm[];
    uint32_t sbase = smem_u32(sm);
    int t = threadIdx.x, l = t & 31, wid = t >> 5;
    int kg = wid >> 3;          // K-group: 0 -> s{0,1}, 1 -> s{2,3}
    int wl = wid & 7;
    int wm = wl & 1, wn = wl >> 1;
    int b = blockIdx.y, n0 = blockIdx.x * 128;
    const float* Ab = g_dist + ((size_t)b * NN + n0) * NN;
    const float* Bt = g_zT + (size_t)b * ND * NN;

    float c[4][4][4];
#pragma unroll
    for (int i = 0; i < 4; i++)
#pragma unroll
        for (int j = 0; j < 4; j++)
#pragma unroll
            for (int k = 0; k < 4; k++) c[i][j][k] = 0.f;

    // stage p: A at p*40960 B, B at p*40960 + 20480 (row stride 40 floats)
#define LOADT(P, K0)                                                             \
    {                                                                            \
        uint32_t as_ = sbase + (P) * 40960u;                                     \
        uint32_t bs_ = as_ + 20480u;                                             \
        _Pragma("unroll")                                                        \
        for (int q = 0; q < 2; q++) {                                            \
            int idx = q * 512 + t;                                               \
            int r_ = idx >> 3;                                                   \
            int f4 = idx & 7;                                                    \
            uint32_t so = (uint32_t)(r_ * 160 + f4 * 16);                        \
            asm volatile("cp.async.cg.shared.global [%0], [%1], 16;"             \
                         :: "r"(as_ + so), "l"(Ab + (size_t)r_ * NN + (K0) + f4 * 4)); \
            asm volatile("cp.async.cg.shared.global [%0], [%1], 16;"             \
                         :: "r"(bs_ + so), "l"(Bt + (size_t)r_ * NN + (K0) + f4 * 4)); \
        }                                                                        \
        asm volatile("cp.async.commit_group;");                                  \
    }

#define COMPUTE(P)                                                               \
    {                                                                            \
        uint32_t as_ = sbase + (P) * 40960u;                                     \
        uint32_t bs_ = as_ + 20480u;                                             \
        _Pragma("unroll")                                                        \
        for (int si = 0; si < 2; si++) {                                         \
            int s = 2 * kg + si;                                                 \
            uint32_t bf[4][2];                                                   \
            _Pragma("unroll")                                                    \
            for (int nt = 0; nt < 4; nt++) {                                     \
                int nrow = wn * 32 + nt * 8 + (l >> 2);                          \
                asm volatile("ld.shared.v2.b32 {%0,%1}, [%2];"                   \
                             : "=r"(bf[nt][0]), "=r"(bf[nt][1])                  \
                             : "r"(bs_ + (uint32_t)((nrow * 40 + s * 8 + 2 * (l & 3)) * 4))); \
            }                                                                    \
            _Pragma("unroll")                                                    \
            for (int mt = 0; mt < 4; mt++) {                                     \
                uint32_t af[4];                                                  \
                int mrow = wm * 64 + mt * 16 + (l >> 2);                         \
                asm volatile("ld.shared.v2.b32 {%0,%1}, [%2];"                   \
                             : "=r"(af[0]), "=r"(af[2])                          \
                             : "r"(as_ + (uint32_t)((mrow * 40 + s * 8 + 2 * (l & 3)) * 4))); \
                asm volatile("ld.shared.v2.b32 {%0,%1}, [%2];"                   \
                             : "=r"(af[1]), "=r"(af[3])                          \
                             : "r"(as_ + (uint32_t)(((mrow + 8) * 40 + s * 8 + 2 * (l & 3)) * 4))); \
                _Pragma("unroll")                                                \
                for (int nt = 0; nt < 4; nt++) {                                 \
                    asm volatile(                                                \
                        "mma.sync.aligned.m16n8k8.row.col.f32.tf32.tf32.f32 "    \
                        "{%0,%1,%2,%3}, {%4,%5,%6,%7}, {%8,%9}, {%0,%1,%2,%3};"  \
                        : "+f"(c[mt][nt][0]), "+f"(c[mt][nt][1]),                \
                          "+f"(c[mt][nt][2]), "+f"(c[mt][nt][3])                 \
                        : "r"(af[0]), "r"(af[1]), "r"(af[2]), "r"(af[3]),        \
                          "r"(bf[nt][0]), "r"(bf[nt][1]));                       \
                }                                                                \
            }                                                                    \
        }                                                                        \
    }

    // 3-stage pipeline prologue: stages 0, 1 in flight
    LOADT(0, 0);
    LOADT(1, BK);
    int p = 0;
    for (int it = 0; it < NIT; it++) {
        if (it + 1 < NIT)
            asm volatile("cp.async.wait_group 1;");
        else
            asm volatile("cp.async.wait_group 0;");
        __syncthreads();
        if (it + 2 < NIT) {
            int pn = (it + 2) % 3;
            LOADT(pn, (it + 2) * BK);
        }
        COMPUTE(p);
        p = (p + 1) % 3;   // NOTE: stage reuse protected by next iter's sync
    }

    // ---- combine split-K partials through smem (stride 132 to dodge banks) ----
    __syncthreads();
    if (kg == 1) {
#pragma unroll
        for (int mt = 0; mt < 4; mt++) {
            int m0 = wm * 64 + mt * 16 + (l >> 2);
#pragma unroll
            for (int nt = 0; nt < 4; nt++) {
                int cc = wn * 32 + nt * 8 + 2 * (l & 3);
                *(float2*)&sm[m0 * 132 + cc] = *(float2*)&c[mt][nt][0];
                *(float2*)&sm[(m0 + 8) * 132 + cc] = *(float2*)&c[mt][nt][2];
            }
        }
    }
    __syncthreads();
    if (kg == 0) {
#pragma unroll
        for (int mt = 0; mt < 4; mt++) {
            int lm0 = wm * 64 + mt * 16 + (l >> 2);
            int r0 = n0 + lm0, r1 = r0 + 8;
            float dv0 = g_dinv[b * NN + r0];
            float dv1 = g_dinv[b * NN + r1];
#pragma unroll
            for (int nt = 0; nt < 4; nt++) {
                int cc = wn * 32 + nt * 8 + 2 * (l & 3);
                float2 p0 = *(const float2*)&sm[lm0 * 132 + cc];
                float2 p1 = *(const float2*)&sm[(lm0 + 8) * 132 + cc];
                float bg0 = bg_l[cc], bg1 = bg_l[cc + 1];
                float z00 = Bt[(size_t)cc * NN + r0];
                float z01 = Bt[(size_t)(cc + 1) * NN + r0];
                float z10 = Bt[(size_t)cc * NN + r1];
                float z11 = Bt[(size_t)(cc + 1) * NN + r1];
                size_t h0o = ((size_t)b * NN + r0) * ND + cc;
                size_t h1o = ((size_t)b * NN + r1) * ND + cc;
                float2 hv0 = *(const float2*)&h[h0o];
                float2 hv1 = *(const float2*)&h[h1o];
                float2 o0, o1;
                o0.x = tanhf(dv0 * (c[mt][nt][0] + p0.x + z00) + bg0) + hv0.x;
                o0.y = tanhf(dv0 * (c[mt][nt][1] + p0.y + z01) + bg1) + hv0.y;
                o1.x = tanhf(dv1 * (c[mt][nt][2] + p1.x + z10) + bg0) + hv1.x;
                o1.y = tanhf(dv1 * (c[mt][nt][3] + p1.y + z11) + bg1) + hv1.y;
                *(float2*)&h[h0o] = o0;
                *(float2*)&h[h1o] = o1;
            }
        }
    }
#undef LOADT
#undef COMPUTE
}

// ---------------------------------------------------------------------------
// Kernel 5: GraphNorm stats per (b, d)
// ---------------------------------------------------------------------------
__global__ void k_stats(const float* __restrict__ h, const float* __restrict__ gna) {
    int b = blockIdx.y;
    int d0 = blockIdx.x * 8;
    int t = threadIdx.x;
    int dc = t & 7, r = t >> 3;
    const float* hb = h + (size_t)b * NN * ND;
    float s = 0.f, q = 0.f;
    for (int k = 0; k < NN; k += 32) {
        float v = hb[(size_t)(k + r) * ND + d0 + dc];
        s += v;
        q = fmaf(v, v, q);
    }
    __shared__ float ss[32][8], sq[32][8];
    ss[r][dc] = s; sq[r][dc] = q;
    __syncthreads();
    for (int off = 16; off > 0; off >>= 1) {
        if (r < off) {
            ss[r][dc] += ss[r + off][dc];
            sq[r][dc] += sq[r + off][dc];
        }
        __syncthreads();
    }
    if (t < 8) {
        float mean = ss[0][t] * (1.f / NN);
        float eh2 = sq[0][t] * (1.f / NN);
        float a = gna[d0 + t];
        float var = eh2 - (2.f * a - a * a) * mean * mean;
        g_mean[b * ND + d0 + t] = mean;
        g_rstd[b * ND + d0 + t] = rsqrtf(var + 1e-5f);
    }
}

// ---------------------------------------------------------------------------
// Kernel 6: normalize in place
// ---------------------------------------------------------------------------
__global__ void k_norm(float* __restrict__ h, const float* __restrict__ gnw,
                       const float* __restrict__ gnb, const float* __restrict__ gna) {
    int idx = blockIdx.x * 256 + threadIdx.x;
    int d = idx & (ND - 1);
    int b = idx >> 18;
    float m = g_mean[b * ND + d];
    float rs = g_rstd[b * ND + d];
    float v = h[idx];
    h[idx] = gnw[d] * (v - gna[d] * m) * rs + gnb[d];
}

// ---------------------------------------------------------------------------
extern "C" void kernel_launch(void* const* d_in, const int* in_sizes, int n_in,
                              void* d_out, int out_size) {
    const float* inst = (const float*)d_in[0];
    const float* Wn   = (const float*)d_in[1];
    const float* bn   = (const float*)d_in[2];
    const float* Wg   = (const float*)d_in[3];
    const float* bg   = (const float*)d_in[4];
    const float* gnw  = (const float*)d_in[5];
    const float* gnb  = (const float*)d_in[6];
    const float* gna  = (const float*)d_in[7];
    float* h = (float*)d_out;

    const int SMEM_DYN = 122880;  // max(3 stages x 40960, 128x132x4 accum)
    static int smem_set = 0;
    if (!smem_set) {
        cudaFuncSetAttribute(k_gemm_mma, cudaFuncAttributeMaxDynamicSharedMemorySize, SMEM_DYN);
        smem_set = 1;
    }

    k_dist<<<dim3(NN, NB), 256>>>(inst);
    k_proj<<<(NB * NN * ND) / 256, 256>>>(inst, Wn, bn, h);
    for (int l = 0; l < 3; l++) {
        k_z<<<NB * NN / 128, 256>>>(h, Wg + l * ND * ND);
        k_gemm_mma<<<dim3(NN / 128, NB), 512, SMEM_DYN>>>(h, bg + l * ND);
        k_stats<<<dim3(ND / 8, NB), 256>>>(h, gna);
        k_norm<<<(NB * NN * ND) / 256, 256>>>(h, gnw, gnb, gna);
    }
}

// round 5
// speedup vs baseline: 1.0507x; 1.0507x over previous
#include <cuda_runtime.h>
#include <cuda_fp16.h>
#include <math.h>
#include <stdint.h>

#define NB 8
#define NN 2048
#define ND 128
#define BK 64
#define NIT (NN / BK)   // 32 k-chunks

// ---- scratch (__device__ globals: allocation-guard safe) ----
// fp16, k-pair-permuted within each 16-element block; diag carries +1 self-loop
__device__ __half g_dist[(size_t)NB * NN * NN];   // 67 MB
__device__ float  g_dinv[NB * NN];
__device__ __half g_zT[(size_t)NB * ND * NN];     // [b][d][m], permuted in m
__device__ float  g_mean[NB * ND];
__device__ float  g_rstd[NB * ND];

__device__ __forceinline__ uint32_t smem_u32(const void* p) {
    uint32_t a;
    asm("{ .reg .u64 t; cvta.to.shared.u64 t, %1; cvt.u32.u64 %0, t; }" : "=r"(a) : "l"(p));
    return a;
}

// logical k within 16-block -> physical position (pair permutation so that an
// LDS.64 at 4q yields logical pairs {2q,2q+1} and {2q+8,2q+9})
__device__ __forceinline__ int kperm(int w) {
    return 4 * ((w & 7) >> 1) + ((w >> 3) << 1) + (w & 1);
}

// FMA-only sqrt (avoids MUFU throughput wall on 33.5M sqrts)
__device__ __forceinline__ float fast_sqrt(float x) {
    float xh = 0.5f * x;
    float y = __int_as_float(0x5f3759df - (__float_as_int(x) >> 1));
    y = y * (1.5f - xh * y * y);
    y = y * (1.5f - xh * y * y);
    y = y * (1.5f - xh * y * y);
    return x * y;
}

// ---------------------------------------------------------------------------
// Kernel 1: dist rows (fp16, permuted, +1 diag) + degree -> dinv
// ---------------------------------------------------------------------------
__global__ void k_dist(const float* __restrict__ inst) {
    int n = blockIdx.x, b = blockIdx.y;
    const float2* xb = (const float2*)(inst + (size_t)b * NN * 2);
    float2 xn = xb[n];
    float sqn = xn.x * xn.x + xn.y * xn.y;
    __half* drow = g_dist + (size_t)(b * NN + n) * NN;
    float acc = 0.f;
    for (int m = threadIdx.x; m < NN; m += 256) {
        float2 xm = xb[m];
        float sqm = xm.x * xm.x + xm.y * xm.y;
        float dot = xn.x * xm.x + xn.y * xm.y;
        float d2 = sqn + sqm - 2.f * dot;
        float d = (d2 > 0.f) ? fast_sqrt(d2) : 0.f;
        acc += d;                           // degree in fp32 (pre-rounding)
        float v = (m == n) ? d + 1.0f : d;  // fold self-loop into A diagonal
        drow[(m & ~15) + kperm(m & 15)] = __float2half_rn(v);
    }
    __shared__ float red[256];
    red[threadIdx.x] = acc;
    __syncthreads();
    for (int s = 128; s > 0; s >>= 1) {
        if (threadIdx.x < s) red[threadIdx.x] += red[threadIdx.x + s];
        __syncthreads();
    }
    if (threadIdx.x == 0)
        g_dinv[b * NN + n] = rsqrtf(1.0f + red[0]);
}

// ---------------------------------------------------------------------------
// Kernel 2: h0 = instance @ Wn^T + bn
// ---------------------------------------------------------------------------
__global__ void k_proj(const float* __restrict__ inst, const float* __restrict__ Wn,
                       const float* __restrict__ bn, float* __restrict__ h) {
    int idx = blockIdx.x * 256 + threadIdx.x;
    int d = idx & (ND - 1);
    int row = idx >> 7;
    float2 x = ((const float2*)inst)[row];
    h[idx] = x.x * Wn[2 * d] + x.y * Wn[2 * d + 1] + bn[d];
}

// ---------------------------------------------------------------------------
// Kernel 3: zT[b][e][m] = dinv[m] * sum_d h[m,d] * Wg[e,d]  (fp16, permuted)
// ---------------------------------------------------------------------------
__global__ void __launch_bounds__(256) k_z(const float* __restrict__ h,
                                           const float* __restrict__ Wg) {
    __shared__ float hT[32][132];
    __shared__ float wT[32][132];
    int t = threadIdx.x;
    int row0 = blockIdx.x * 128;  // global row over NB*NN
    int rg = t >> 4, cg = t & 15;
    float acc[8][8];
#pragma unroll
    for (int i = 0; i < 8; i++)
#pragma unroll
        for (int j = 0; j < 8; j++) acc[i][j] = 0.f;

    for (int dc = 0; dc < ND; dc += 32) {
        __syncthreads();
#pragma unroll
        for (int k = t; k < 128 * 32; k += 256) {
            int r = k >> 5, dd = k & 31;
            hT[dd][r] = h[(size_t)(row0 + r) * ND + dc + dd];
        }
#pragma unroll
        for (int k = t; k < 128 * 32; k += 256) {
            int e = k >> 5, dd = k & 31;
            wT[dd][e] = Wg[e * ND + dc + dd];
        }
        __syncthreads();
#pragma unroll
        for (int dd = 0; dd < 32; dd++) {
            float4 a0 = *(const float4*)&hT[dd][8 * rg];
            float4 a1 = *(const float4*)&hT[dd][8 * rg + 4];
            float4 b0 = *(const float4*)&wT[dd][8 * cg];
            float4 b1 = *(const float4*)&wT[dd][8 * cg + 4];
            float a[8] = {a0.x, a0.y, a0.z, a0.w, a1.x, a1.y, a1.z, a1.w};
            float bb[8] = {b0.x, b0.y, b0.z, b0.w, b1.x, b1.y, b1.z, b1.w};
#pragma unroll
            for (int i = 0; i < 8; i++)
#pragma unroll
                for (int j = 0; j < 8; j++)
                    acc[i][j] = fmaf(a[i], bb[j], acc[i][j]);
        }
    }
    int b = row0 >> 11;            // NN = 2048
    int m0 = (row0 & (NN - 1)) + 8 * rg;   // multiple of 8
    __half* zTb = g_zT + (size_t)b * ND * NN;
    float dvv[8];
#pragma unroll
    for (int i = 0; i < 8; i++) dvv[i] = g_dinv[b * NN + m0 + i];
    int base16 = m0 & ~15;
    int off8 = (m0 & 8) ? 2 : 0;
#pragma unroll
    for (int j = 0; j < 8; j++) {
        int d = 8 * cg + j;
        size_t rb = (size_t)d * NN + base16 + off8;
#pragma unroll
        for (int u = 0; u < 4; u++) {
            __half2 v = __floats2half2_rn(acc[2 * u][j] * dvv[2 * u],
                                          acc[2 * u + 1][j] * dvv[2 * u + 1]);
            *(__half2*)(zTb + rb + 4 * u) = v;
        }
    }
}

// ---------------------------------------------------------------------------
// Kernel 4: fp16 m16n8k16 mma.sync GEMM.
// h[n,:] = tanh( dinv[n]*((dist+I)[n,:] @ z) + bg ) + h[n,:]
// CTA 128x128, 8 warps (2x4), warp tile 64x32, BK=64, 3-stage cp.async.
// 128B smem rows (64 halves), no pad: conflict-free LDS.64 fragments thanks
// to the global k-pair permutation (lo b32 = pair q, hi b32 = pair q+4).
// ---------------------------------------------------------------------------
__global__ void __launch_bounds__(256) k_gemm_mma(float* __restrict__ h,
                                                  const float* __restrict__ bg_l) {
    extern __shared__ char smc[];
    uint32_t sbase = smem_u32(smc);
    int t = threadIdx.x, l = t & 31, wid = t >> 5;
    int wm = wid & 1, wn = wid >> 1;
    int b = blockIdx.y, n0 = blockIdx.x * 128;
    const __half* Ab = g_dist + ((size_t)b * NN + n0) * NN;
    const __half* Bt = g_zT + (size_t)b * ND * NN;

    float c[4][4][4];
#pragma unroll
    for (int i = 0; i < 4; i++)
#pragma unroll
        for (int j = 0; j < 4; j++)
#pragma unroll
            for (int k = 0; k < 4; k++) c[i][j][k] = 0.f;

    // stage p: A at p*32768 (16KB), B at p*32768+16384
#define LOADT(P, K0)                                                             \
    {                                                                            \
        uint32_t as_ = sbase + (P) * 32768u;                                     \
        uint32_t bs_ = as_ + 16384u;                                             \
        _Pragma("unroll")                                                        \
        for (int q = 0; q < 4; q++) {                                            \
            int idx = q * 256 + t;                                               \
            int r_ = idx >> 3;                                                   \
            int c16 = idx & 7;                                                   \
            uint32_t so = (uint32_t)(r_ * 128 + c16 * 16);                       \
            asm volatile("cp.async.cg.shared.global [%0], [%1], 16;"             \
                         :: "r"(as_ + so), "l"(Ab + (size_t)r_ * NN + (K0) + c16 * 8)); \
            asm volatile("cp.async.cg.shared.global [%0], [%1], 16;"             \
                         :: "r"(bs_ + so), "l"(Bt + (size_t)r_ * NN + (K0) + c16 * 8)); \
        }                                                                        \
        asm volatile("cp.async.commit_group;");                                  \
    }

#define COMPUTE(P)                                                               \
    {                                                                            \
        uint32_t as_ = sbase + (P) * 32768u;                                     \
        uint32_t bs_ = as_ + 16384u;                                             \
        _Pragma("unroll")                                                        \
        for (int s = 0; s < 4; s++) {                                            \
            uint32_t bf[4][2];                                                   \
            _Pragma("unroll")                                                    \
            for (int nt = 0; nt < 4; nt++) {                                     \
                int nrow = wn * 32 + nt * 8 + (l >> 2);                          \
                asm volatile("ld.shared.v2.b32 {%0,%1}, [%2];"                   \
                             : "=r"(bf[nt][0]), "=r"(bf[nt][1])                  \
                             : "r"(bs_ + (uint32_t)(nrow * 128 + s * 32 + (l & 3) * 8))); \
            }                                                                    \
            _Pragma("unroll")                                                    \
            for (int mt = 0; mt < 4; mt++) {                                     \
                uint32_t af[4];                                                  \
                int mrow = wm * 64 + mt * 16 + (l >> 2);                         \
                asm volatile("ld.shared.v2.b32 {%0,%1}, [%2];"                   \
                             : "=r"(af[0]), "=r"(af[2])                          \
                             : "r"(as_ + (uint32_t)(mrow * 128 + s * 32 + (l & 3) * 8))); \
                asm volatile("ld.shared.v2.b32 {%0,%1}, [%2];"                   \
                             : "=r"(af[1]), "=r"(af[3])                          \
                             : "r"(as_ + (uint32_t)((mrow + 8) * 128 + s * 32 + (l & 3) * 8))); \
                _Pragma("unroll")                                                \
                for (int nt = 0; nt < 4; nt++) {                                 \
                    asm volatile(                                                \
                        "mma.sync.aligned.m16n8k16.row.col.f32.f16.f16.f32 "     \
                        "{%0,%1,%2,%3}, {%4,%5,%6,%7}, {%8,%9}, {%0,%1,%2,%3};"  \
                        : "+f"(c[mt][nt][0]), "+f"(c[mt][nt][1]),                \
                          "+f"(c[mt][nt][2]), "+f"(c[mt][nt][3])                 \
                        : "r"(af[0]), "r"(af[1]), "r"(af[2]), "r"(af[3]),        \
                          "r"(bf[nt][0]), "r"(bf[nt][1]));                       \
                }                                                                \
            }                                                                    \
        }                                                                        \
    }

    // 3-stage pipeline: stages 0,1 in flight
    LOADT(0, 0);
    LOADT(1, BK);
    int p = 0;
    for (int it = 0; it < NIT; it++) {
        if (it + 1 < NIT)
            asm volatile("cp.async.wait_group 1;");
        else
            asm volatile("cp.async.wait_group 0;");
        __syncthreads();
        if (it + 2 < NIT) {
            int pn = (it + 2) % 3;
            LOADT(pn, (it + 2) * BK);
        }
        COMPUTE(p);
        p = (p + 1) % 3;
    }

    // epilogue: dinv + bias + tanh + residual (self-loop already in A diag)
#pragma unroll
    for (int mt = 0; mt < 4; mt++) {
        int r0 = n0 + wm * 64 + mt * 16 + (l >> 2);
        int r1 = r0 + 8;
        float dv0 = g_dinv[b * NN + r0];
        float dv1 = g_dinv[b * NN + r1];
#pragma unroll
        for (int nt = 0; nt < 4; nt++) {
            int cc = wn * 32 + nt * 8 + 2 * (l & 3);
            float bg0 = bg_l[cc], bg1 = bg_l[cc + 1];
            size_t h0o = ((size_t)b * NN + r0) * ND + cc;
            size_t h1o = ((size_t)b * NN + r1) * ND + cc;
            float2 hv0 = *(const float2*)&h[h0o];
            float2 hv1 = *(const float2*)&h[h1o];
            float2 o0, o1;
            o0.x = tanhf(dv0 * c[mt][nt][0] + bg0) + hv0.x;
            o0.y = tanhf(dv0 * c[mt][nt][1] + bg1) + hv0.y;
            o1.x = tanhf(dv1 * c[mt][nt][2] + bg0) + hv1.x;
            o1.y = tanhf(dv1 * c[mt][nt][3] + bg1) + hv1.y;
            *(float2*)&h[h0o] = o0;
            *(float2*)&h[h1o] = o1;
        }
    }
#undef LOADT
#undef COMPUTE
}

// ---------------------------------------------------------------------------
// Kernel 5: GraphNorm stats per (b, d)
// ---------------------------------------------------------------------------
__global__ void k_stats(const float* __restrict__ h, const float* __restrict__ gna) {
    int b = blockIdx.y;
    int d0 = blockIdx.x * 8;
    int t = threadIdx.x;
    int dc = t & 7, r = t >> 3;
    const float* hb = h + (size_t)b * NN * ND;
    float s = 0.f, q = 0.f;
    for (int k = 0; k < NN; k += 32) {
        float v = hb[(size_t)(k + r) * ND + d0 + dc];
        s += v;
        q = fmaf(v, v, q);
    }
    __shared__ float ss[32][8], sq[32][8];
    ss[r][dc] = s; sq[r][dc] = q;
    __syncthreads();
    for (int off = 16; off > 0; off >>= 1) {
        if (r < off) {
            ss[r][dc] += ss[r + off][dc];
            sq[r][dc] += sq[r + off][dc];
        }
        __syncthreads();
    }
    if (t < 8) {
        float mean = ss[0][t] * (1.f / NN);
        float eh2 = sq[0][t] * (1.f / NN);
        float a = gna[d0 + t];
        float var = eh2 - (2.f * a - a * a) * mean * mean;
        g_mean[b * ND + d0 + t] = mean;
        g_rstd[b * ND + d0 + t] = rsqrtf(var + 1e-5f);
    }
}

// ---------------------------------------------------------------------------
// Kernel 6: normalize in place
// ---------------------------------------------------------------------------
__global__ void k_norm(float* __restrict__ h, const float* __restrict__ gnw,
                       const float* __restrict__ gnb, const float* __restrict__ gna) {
    int idx = blockIdx.x * 256 + threadIdx.x;
    int d = idx & (ND - 1);
    int b = idx >> 18;
    float m = g_mean[b * ND + d];
    float rs = g_rstd[b * ND + d];
    float v = h[idx];
    h[idx] = gnw[d] * (v - gna[d] * m) * rs + gnb[d];
}

// ---------------------------------------------------------------------------
extern "C" void kernel_launch(void* const* d_in, const int* in_sizes, int n_in,
                              void* d_out, int out_size) {
    const float* inst = (const float*)d_in[0];
    const float* Wn   = (const float*)d_in[1];
    const float* bn   = (const float*)d_in[2];
    const float* Wg   = (const float*)d_in[3];
    const float* bg   = (const float*)d_in[4];
    const float* gnw  = (const float*)d_in[5];
    const float* gnb  = (const float*)d_in[6];
    const float* gna  = (const float*)d_in[7];
    float* h = (float*)d_out;

    const int SMEM_DYN = 3 * 32768;  // 3 stages x (A 16KB + B 16KB)
    static int smem_set = 0;
    if (!smem_set) {
        cudaFuncSetAttribute(k_gemm_mma, cudaFuncAttributeMaxDynamicSharedMemorySize, SMEM_DYN);
        smem_set = 1;
    }

    k_dist<<<dim3(NN, NB), 256>>>(inst);
    k_proj<<<(NB * NN * ND) / 256, 256>>>(inst, Wn, bn, h);
    for (int l = 0; l < 3; l++) {
        k_z<<<NB * NN / 128, 256>>>(h, Wg + l * ND * ND);
        k_gemm_mma<<<dim3(NN / 128, NB), 256, SMEM_DYN>>>(h, bg + l * ND);
        k_stats<<<dim3(ND / 8, NB), 256>>>(h, gna);
        k_norm<<<(NB * NN * ND) / 256, 256>>>(h, gnw, gnb, gna);
    }
}

// round 6
// speedup vs baseline: 1.3897x; 1.3227x over previous
#include <cuda_runtime.h>
#include <cuda_fp16.h>
#include <math.h>
#include <stdint.h>

#define NB 8
#define NN 2048
#define ND 128
#define BK 64
#define NIT (NN / BK)   // 32 k-chunks
#define ROWB 160u       // smem row stride bytes (80 halves) -> conflict-free LDS.64

// ---- scratch (__device__ globals: allocation-guard safe) ----
// fp16, k-pair-permuted within each 16-element block; diag carries +1 self-loop
__device__ __half g_dist[(size_t)NB * NN * NN];   // 67 MB
__device__ float  g_dinv[NB * NN];
__device__ __half g_zT[(size_t)NB * ND * NN];     // [b][d][m], permuted in m
__device__ float  g_mean[NB * ND];
__device__ float  g_rstd[NB * ND];

__device__ __forceinline__ uint32_t smem_u32(const void* p) {
    uint32_t a;
    asm("{ .reg .u64 t; cvta.to.shared.u64 t, %1; cvt.u32.u64 %0, t; }" : "=r"(a) : "l"(p));
    return a;
}

// logical k within 16-block -> physical position (pair permutation so that an
// LDS.64 at 4q yields logical pairs {2q,2q+1} and {2q+8,2q+9})
__device__ __forceinline__ int kperm(int w) {
    return 4 * ((w & 7) >> 1) + ((w >> 3) << 1) + (w & 1);
}

// FMA-only sqrt (avoids MUFU throughput wall on 33.5M sqrts)
__device__ __forceinline__ float fast_sqrt(float x) {
    float xh = 0.5f * x;
    float y = __int_as_float(0x5f3759df - (__float_as_int(x) >> 1));
    y = y * (1.5f - xh * y * y);
    y = y * (1.5f - xh * y * y);
    y = y * (1.5f - xh * y * y);
    return x * y;
}

// ---------------------------------------------------------------------------
// Kernel 1: dist rows (fp16, permuted, +1 diag) + degree -> dinv
// ---------------------------------------------------------------------------
__global__ void k_dist(const float* __restrict__ inst) {
    int n = blockIdx.x, b = blockIdx.y;
    const float2* xb = (const float2*)(inst + (size_t)b * NN * 2);
    float2 xn = xb[n];
    float sqn = xn.x * xn.x + xn.y * xn.y;
    __half* drow = g_dist + (size_t)(b * NN + n) * NN;
    float acc = 0.f;
    for (int m = threadIdx.x; m < NN; m += 256) {
        float2 xm = xb[m];
        float sqm = xm.x * xm.x + xm.y * xm.y;
        float dot = xn.x * xm.x + xn.y * xm.y;
        float d2 = sqn + sqm - 2.f * dot;
        float d = (d2 > 0.f) ? fast_sqrt(d2) : 0.f;
        acc += d;                           // degree in fp32 (pre-rounding)
        float v = (m == n) ? d + 1.0f : d;  // fold self-loop into A diagonal
        drow[(m & ~15) + kperm(m & 15)] = __float2half_rn(v);
    }
    __shared__ float red[256];
    red[threadIdx.x] = acc;
    __syncthreads();
    for (int s = 128; s > 0; s >>= 1) {
        if (threadIdx.x < s) red[threadIdx.x] += red[threadIdx.x + s];
        __syncthreads();
    }
    if (threadIdx.x == 0)
        g_dinv[b * NN + n] = rsqrtf(1.0f + red[0]);
}

// ---------------------------------------------------------------------------
// Kernel 2: h0 = instance @ Wn^T + bn
// ---------------------------------------------------------------------------
__global__ void k_proj(const float* __restrict__ inst, const float* __restrict__ Wn,
                       const float* __restrict__ bn, float* __restrict__ h) {
    int idx = blockIdx.x * 256 + threadIdx.x;
    int d = idx & (ND - 1);
    int row = idx >> 7;
    float2 x = ((const float2*)inst)[row];
    h[idx] = x.x * Wn[2 * d] + x.y * Wn[2 * d + 1] + bn[d];
}

// ---------------------------------------------------------------------------
// Kernel 3: zT[b][e][m] = dinv[m] * sum_d h[m,d] * Wg[e,d]  (fp16, permuted)
// ---------------------------------------------------------------------------
__global__ void __launch_bounds__(256) k_z(const float* __restrict__ h,
                                           const float* __restrict__ Wg) {
    __shared__ float hT[32][132];
    __shared__ float wT[32][132];
    int t = threadIdx.x;
    int row0 = blockIdx.x * 128;  // global row over NB*NN
    int rg = t >> 4, cg = t & 15;
    float acc[8][8];
#pragma unroll
    for (int i = 0; i < 8; i++)
#pragma unroll
        for (int j = 0; j < 8; j++) acc[i][j] = 0.f;

    for (int dc = 0; dc < ND; dc += 32) {
        __syncthreads();
#pragma unroll
        for (int k = t; k < 128 * 32; k += 256) {
            int r = k >> 5, dd = k & 31;
            hT[dd][r] = h[(size_t)(row0 + r) * ND + dc + dd];
        }
#pragma unroll
        for (int k = t; k < 128 * 32; k += 256) {
            int e = k >> 5, dd = k & 31;
            wT[dd][e] = Wg[e * ND + dc + dd];
        }
        __syncthreads();
#pragma unroll
        for (int dd = 0; dd < 32; dd++) {
            float4 a0 = *(const float4*)&hT[dd][8 * rg];
            float4 a1 = *(const float4*)&hT[dd][8 * rg + 4];
            float4 b0 = *(const float4*)&wT[dd][8 * cg];
            float4 b1 = *(const float4*)&wT[dd][8 * cg + 4];
            float a[8] = {a0.x, a0.y, a0.z, a0.w, a1.x, a1.y, a1.z, a1.w};
            float bb[8] = {b0.x, b0.y, b0.z, b0.w, b1.x, b1.y, b1.z, b1.w};
#pragma unroll
            for (int i = 0; i < 8; i++)
#pragma unroll
                for (int j = 0; j < 8; j++)
                    acc[i][j] = fmaf(a[i], bb[j], acc[i][j]);
        }
    }
    int b = row0 >> 11;            // NN = 2048
    int m0 = (row0 & (NN - 1)) + 8 * rg;   // multiple of 8
    __half* zTb = g_zT + (size_t)b * ND * NN;
    float dvv[8];
#pragma unroll
    for (int i = 0; i < 8; i++) dvv[i] = g_dinv[b * NN + m0 + i];
    int base16 = m0 & ~15;
    int off8 = (m0 & 8) ? 2 : 0;
#pragma unroll
    for (int j = 0; j < 8; j++) {
        int d = 8 * cg + j;
        size_t rb = (size_t)d * NN + base16 + off8;
#pragma unroll
        for (int u = 0; u < 4; u++) {
            __half2 v = __floats2half2_rn(acc[2 * u][j] * dvv[2 * u],
                                          acc[2 * u + 1][j] * dvv[2 * u + 1]);
            *(__half2*)(zTb + rb + 4 * u) = v;
        }
    }
}

// ---------------------------------------------------------------------------
// Kernel 4: fp16 m16n8k16 mma.sync GEMM.
// h[n,:] = tanh( dinv[n]*((dist+I)[n,:] @ z) + bg ) + h[n,:]
// CTA 128x128, 8 warps (2x4), warp tile 64x32, BK=64, 3-stage cp.async.
// Smem rows padded to 160 B: fragment LDS.64 bank index = 8*(l>>2)+2*(l&3)
// per 16-lane phase -> conflict-free (the 128B-row layout was 4-way conflicted).
// ---------------------------------------------------------------------------
__global__ void __launch_bounds__(256) k_gemm_mma(float* __restrict__ h,
                                                  const float* __restrict__ bg_l) {
    extern __shared__ char smc[];
    uint32_t sbase = smem_u32(smc);
    int t = threadIdx.x, l = t & 31, wid = t >> 5;
    int wm = wid & 1, wn = wid >> 1;
    int b = blockIdx.y, n0 = blockIdx.x * 128;
    const __half* Ab = g_dist + ((size_t)b * NN + n0) * NN;
    const __half* Bt = g_zT + (size_t)b * ND * NN;

    float c[4][4][4];
#pragma unroll
    for (int i = 0; i < 4; i++)
#pragma unroll
        for (int j = 0; j < 4; j++)
#pragma unroll
            for (int k = 0; k < 4; k++) c[i][j][k] = 0.f;

    // stage p: A at p*40960 (128 rows x 160B), B at p*40960 + 20480
#define LOADT(P, K0)                                                             \
    {                                                                            \
        uint32_t as_ = sbase + (P) * 40960u;                                     \
        uint32_t bs_ = as_ + 20480u;                                             \
        _Pragma("unroll")                                                        \
        for (int q = 0; q < 4; q++) {                                            \
            int idx = q * 256 + t;                                               \
            int r_ = idx >> 3;                                                   \
            int c16 = idx & 7;                                                   \
            uint32_t so = (uint32_t)(r_ * ROWB + c16 * 16);                      \
            asm volatile("cp.async.cg.shared.global [%0], [%1], 16;"             \
                         :: "r"(as_ + so), "l"(Ab + (size_t)r_ * NN + (K0) + c16 * 8)); \
            asm volatile("cp.async.cg.shared.global [%0], [%1], 16;"             \
                         :: "r"(bs_ + so), "l"(Bt + (size_t)r_ * NN + (K0) + c16 * 8)); \
        }                                                                        \
        asm volatile("cp.async.commit_group;");                                  \
    }

#define COMPUTE(P)                                                               \
    {                                                                            \
        uint32_t as_ = sbase + (P) * 40960u;                                     \
        uint32_t bs_ = as_ + 20480u;                                             \
        _Pragma("unroll")                                                        \
        for (int s = 0; s < 4; s++) {                                            \
            uint32_t bf[4][2];                                                   \
            _Pragma("unroll")                                                    \
            for (int nt = 0; nt < 4; nt++) {                                     \
                int nrow = wn * 32 + nt * 8 + (l >> 2);                          \
                asm volatile("ld.shared.v2.b32 {%0,%1}, [%2];"                   \
                             : "=r"(bf[nt][0]), "=r"(bf[nt][1])                  \
                             : "r"(bs_ + (uint32_t)(nrow * ROWB + s * 32 + (l & 3) * 8))); \
            }                                                                    \
            _Pragma("unroll")                                                    \
            for (int mt = 0; mt < 4; mt++) {                                     \
                uint32_t af[4];                                                  \
                int mrow = wm * 64 + mt * 16 + (l >> 2);                         \
                asm volatile("ld.shared.v2.b32 {%0,%1}, [%2];"                   \
                             : "=r"(af[0]), "=r"(af[2])                          \
                             : "r"(as_ + (uint32_t)(mrow * ROWB + s * 32 + (l & 3) * 8))); \
                asm volatile("ld.shared.v2.b32 {%0,%1}, [%2];"                   \
                             : "=r"(af[1]), "=r"(af[3])                          \
                             : "r"(as_ + (uint32_t)((mrow + 8) * ROWB + s * 32 + (l & 3) * 8))); \
                _Pragma("unroll")                                                \
                for (int nt = 0; nt < 4; nt++) {                                 \
                    asm volatile(                                                \
                        "mma.sync.aligned.m16n8k16.row.col.f32.f16.f16.f32 "     \
                        "{%0,%1,%2,%3}, {%4,%5,%6,%7}, {%8,%9}, {%0,%1,%2,%3};"  \
                        : "+f"(c[mt][nt][0]), "+f"(c[mt][nt][1]),                \
                          "+f"(c[mt][nt][2]), "+f"(c[mt][nt][3])                 \
                        : "r"(af[0]), "r"(af[1]), "r"(af[2]), "r"(af[3]),        \
                          "r"(bf[nt][0]), "r"(bf[nt][1]));                       \
                }                                                                \
            }                                                                    \
        }                                                                        \
    }

    // 3-stage pipeline: stages 0,1 in flight
    LOADT(0, 0);
    LOADT(1, BK);
    int p = 0;
    for (int it = 0; it < NIT; it++) {
        if (it + 1 < NIT)
            asm volatile("cp.async.wait_group 1;");
        else
            asm volatile("cp.async.wait_group 0;");
        __syncthreads();
        if (it + 2 < NIT) {
            int pn = (it + 2) % 3;
            LOADT(pn, (it + 2) * BK);
        }
        COMPUTE(p);
        p = (p + 1) % 3;
    }

    // epilogue: dinv + bias + tanh + residual (self-loop already in A diag)
#pragma unroll
    for (int mt = 0; mt < 4; mt++) {
        int r0 = n0 + wm * 64 + mt * 16 + (l >> 2);
        int r1 = r0 + 8;
        float dv0 = g_dinv[b * NN + r0];
        float dv1 = g_dinv[b * NN + r1];
#pragma unroll
        for (int nt = 0; nt < 4; nt++) {
            int cc = wn * 32 + nt * 8 + 2 * (l & 3);
            float bg0 = bg_l[cc], bg1 = bg_l[cc + 1];
            size_t h0o = ((size_t)b * NN + r0) * ND + cc;
            size_t h1o = ((size_t)b * NN + r1) * ND + cc;
            float2 hv0 = *(const float2*)&h[h0o];
            float2 hv1 = *(const float2*)&h[h1o];
            float2 o0, o1;
            o0.x = tanhf(dv0 * c[mt][nt][0] + bg0) + hv0.x;
            o0.y = tanhf(dv0 * c[mt][nt][1] + bg1) + hv0.y;
            o1.x = tanhf(dv1 * c[mt][nt][2] + bg0) + hv1.x;
            o1.y = tanhf(dv1 * c[mt][nt][3] + bg1) + hv1.y;
            *(float2*)&h[h0o] = o0;
            *(float2*)&h[h1o] = o1;
        }
    }
#undef LOADT
#undef COMPUTE
}

// ---------------------------------------------------------------------------
// Kernel 5: GraphNorm stats per (b, d)
// ---------------------------------------------------------------------------
__global__ void k_stats(const float* __restrict__ h, const float* __restrict__ gna) {
    int b = blockIdx.y;
    int d0 = blockIdx.x * 8;
    int t = threadIdx.x;
    int dc = t & 7, r = t >> 3;
    const float* hb = h + (size_t)b * NN * ND;
    float s = 0.f, q = 0.f;
    for (int k = 0; k < NN; k += 32) {
        float v = hb[(size_t)(k + r) * ND + d0 + dc];
        s += v;
        q = fmaf(v, v, q);
    }
    __shared__ float ss[32][8], sq[32][8];
    ss[r][dc] = s; sq[r][dc] = q;
    __syncthreads();
    for (int off = 16; off > 0; off >>= 1) {
        if (r < off) {
            ss[r][dc] += ss[r + off][dc];
            sq[r][dc] += sq[r + off][dc];
        }
        __syncthreads();
    }
    if (t < 8) {
        float mean = ss[0][t] * (1.f / NN);
        float eh2 = sq[0][t] * (1.f / NN);
        float a = gna[d0 + t];
        float var = eh2 - (2.f * a - a * a) * mean * mean;
        g_mean[b * ND + d0 + t] = mean;
        g_rstd[b * ND + d0 + t] = rsqrtf(var + 1e-5f);
    }
}

// ---------------------------------------------------------------------------
// Kernel 6: normalize in place
// ---------------------------------------------------------------------------
__global__ void k_norm(float* __restrict__ h, const float* __restrict__ gnw,
                       const float* __restrict__ gnb, const float* __restrict__ gna) {
    int idx = blockIdx.x * 256 + threadIdx.x;
    int d = idx & (ND - 1);
    int b = idx >> 18;
    float m = g_mean[b * ND + d];
    float rs = g_rstd[b * ND + d];
    float v = h[idx];
    h[idx] = gnw[d] * (v - gna[d] * m) * rs + gnb[d];
}

// ---------------------------------------------------------------------------
extern "C" void kernel_launch(void* const* d_in, const int* in_sizes, int n_in,
                              void* d_out, int out_size) {
    const float* inst = (const float*)d_in[0];
    const float* Wn   = (const float*)d_in[1];
    const float* bn   = (const float*)d_in[2];
    const float* Wg   = (const float*)d_in[3];
    const float* bg   = (const float*)d_in[4];
    const float* gnw  = (const float*)d_in[5];
    const float* gnb  = (const float*)d_in[6];
    const float* gna  = (const float*)d_in[7];
    float* h = (float*)d_out;

    const int SMEM_DYN = 3 * 40960;  // 3 stages x (A 20KB + B 20KB), 160B rows
    static int smem_set = 0;
    if (!smem_set) {
        cudaFuncSetAttribute(k_gemm_mma, cudaFuncAttributeMaxDynamicSharedMemorySize, SMEM_DYN);
        smem_set = 1;
    }

    k_dist<<<dim3(NN, NB), 256>>>(inst);
    k_proj<<<(NB * NN * ND) / 256, 256>>>(inst, Wn, bn, h);
    for (int l = 0; l < 3; l++) {
        k_z<<<NB * NN / 128, 256>>>(h, Wg + l * ND * ND);
        k_gemm_mma<<<dim3(NN / 128, NB), 256, SMEM_DYN>>>(h, bg + l * ND);
        k_stats<<<dim3(ND / 8, NB), 256>>>(h, gna);
        k_norm<<<(NB * NN * ND) / 256, 256>>>(h, gnw, gnb, gna);
    }
}